// round 1
// baseline (speedup 1.0000x reference)
#include <cuda_runtime.h>
#include <math.h>

// Problem shape (fixed by the dataset)
#define NB 8
#define NT 4096
#define NH 8
#define ND 64
#define NC 64                 // chunks along T
#define NL (NT / NC)          // 64 timesteps per chunk
#define F4T (NH * ND / 4)     // float4 stride between consecutive t = 128

// Scratch: chunk aggregates and chunk-entry carries. [B,H,C,D] as float4.
__device__ float4 g_partials[NB * NH * NC * ND / 4];
__device__ float4 g_carries [NB * NH * NC * ND / 4];

__device__ __forceinline__ float sigf(float x) { return 1.0f / (1.0f + expf(-x)); }

// Kernel 1: per-chunk local scan starting from 0; emit aggregate S_c.
// block = 64 threads: 4 chunk-lanes x 16 d-quads (float4 over D).
__global__ __launch_bounds__(64) void k_partials(const float4* __restrict__ v,
                                                 const float4* __restrict__ x,
                                                 const float*  __restrict__ sw)
{
    int tid = threadIdx.x;
    int sub = tid >> 4;                 // which chunk within this block
    int dq  = tid & 15;                 // d / 4
    int c   = blockIdx.x * 4 + sub;
    int bh  = blockIdx.y;               // b*H + h
    int h   = bh & (NH - 1);
    int b   = bh >> 3;

    float a  = sigf(sw[h]);
    float om = 1.0f - a;
    float cf = a * (om / fmaxf(om, 1e-6f));   // coefficient on aux

    int base = ((b * NT + c * NL) * NH + h) * (ND / 4) + dq;

    float4 y = make_float4(0.f, 0.f, 0.f, 0.f);
    #pragma unroll 8
    for (int i = 0; i < NL; ++i) {
        float4 vv = v[base + i * F4T];
        float4 xx = x[base + i * F4T];
        y.x = fmaf(a, y.x, fmaf(om, vv.x, cf * xx.x));
        y.y = fmaf(a, y.y, fmaf(om, vv.y, cf * xx.y));
        y.z = fmaf(a, y.z, fmaf(om, vv.z, cf * xx.z));
        y.w = fmaf(a, y.w, fmaf(om, vv.w, cf * xx.w));
    }
    g_partials[(bh * NC + c) * 16 + dq] = y;
}

// Kernel 2: scan chunk aggregates per channel.
// carry[0] = v0 ; carry[c] = a^L * carry[c-1] + S[c-1].
__global__ __launch_bounds__(16) void k_carry(const float*  __restrict__ sw,
                                              const float4* __restrict__ v0)
{
    int bh = blockIdx.x;
    int h  = bh & (NH - 1);
    int dq = threadIdx.x;               // 0..15

    float a  = sigf(sw[h]);
    float aL = a;
    #pragma unroll
    for (int i = 0; i < 6; ++i) aL *= aL;   // a^64 via repeated squaring

    float4 carry = v0[h * 16 + dq];         // y[-1] = v0 (broadcast over b)
    for (int c = 0; c < NC; ++c) {
        int idx = (bh * NC + c) * 16 + dq;
        g_carries[idx] = carry;             // y at entry of chunk c
        float4 S = g_partials[idx];
        carry.x = fmaf(aL, carry.x, S.x);
        carry.y = fmaf(aL, carry.y, S.y);
        carry.z = fmaf(aL, carry.z, S.z);
        carry.w = fmaf(aL, carry.w, S.w);
    }
}

// Kernel 3: local scan seeded with the carry; write output.
__global__ __launch_bounds__(64) void k_final(const float4* __restrict__ v,
                                              const float4* __restrict__ x,
                                              const float*  __restrict__ sw,
                                              float4*       __restrict__ out)
{
    int tid = threadIdx.x;
    int sub = tid >> 4;
    int dq  = tid & 15;
    int c   = blockIdx.x * 4 + sub;
    int bh  = blockIdx.y;
    int h   = bh & (NH - 1);
    int b   = bh >> 3;

    float a  = sigf(sw[h]);
    float om = 1.0f - a;
    float cf = a * (om / fmaxf(om, 1e-6f));

    int base = ((b * NT + c * NL) * NH + h) * (ND / 4) + dq;

    float4 y = g_carries[(bh * NC + c) * 16 + dq];
    #pragma unroll 8
    for (int i = 0; i < NL; ++i) {
        float4 vv = v[base + i * F4T];
        float4 xx = x[base + i * F4T];
        y.x = fmaf(a, y.x, fmaf(om, vv.x, cf * xx.x));
        y.y = fmaf(a, y.y, fmaf(om, vv.y, cf * xx.y));
        y.z = fmaf(a, y.z, fmaf(om, vv.z, cf * xx.z));
        y.w = fmaf(a, y.w, fmaf(om, vv.w, cf * xx.w));
        out[base + i * F4T] = y;
    }
}

extern "C" void kernel_launch(void* const* d_in, const int* in_sizes, int n_in,
                              void* d_out, int out_size)
{
    const float4* v  = (const float4*)d_in[0];   // values   [B,T,H,D] f32
    const float4* x  = (const float4*)d_in[1];   // aux      [B,T,H,D] f32
    const float4* v0 = (const float4*)d_in[2];   // v0       [1,1,H,D] f32
    const float*  sw = (const float*)d_in[3];    // weight   [H,1]     f32
    float4* out = (float4*)d_out;

    dim3 grid(NC / 4, NB * NH);                  // 16 x 64 = 1024 blocks
    k_partials<<<grid, 64>>>(v, x, sw);
    k_carry<<<NB * NH, 16>>>(sw, v0);
    k_final<<<grid, 64>>>(v, x, sw, out);
}

// round 3
// speedup vs baseline: 1.9464x; 1.9464x over previous
#include <cuda_runtime.h>
#include <math.h>

// Shape (fixed by the dataset)
#define NB 8
#define NT 4096
#define NH 8
#define ND 64
#define DQ 16                 // float4 lanes over D
#define L 8                   // timesteps per thread
#define SUBS 32               // sub-chunks per tile (block = SUBS*DQ = 512 threads)
#define TILE_T (L * SUBS)     // 256 timesteps per tile
#define NTILES (NT / TILE_T)  // 16
#define NBH (NB * NH)         // 64
#define F4T (NH * ND / 4)     // float4 stride between consecutive t = 128

// Decoupled-lookback state (per tile, per channel)
__device__ float4 g_S[NTILES * NBH * DQ];   // tile aggregate
__device__ float4 g_Y[NTILES * NBH * DQ];   // tile inclusive end value
__device__ int    g_flag[NTILES * NBH];     // 0 = empty, 1 = A, 2 = P

static __device__ __forceinline__ void st_release(int* p, int v) {
    asm volatile("st.release.gpu.s32 [%0], %1;" :: "l"(p), "r"(v) : "memory");
}
static __device__ __forceinline__ int ld_acquire(const int* p) {
    int v;
    asm volatile("ld.acquire.gpu.s32 %0, [%1];" : "=r"(v) : "l"(p) : "memory");
    return v;
}

__global__ void k_zero() { g_flag[threadIdx.x] = 0; }   // 1024 = NTILES*NBH threads

__global__ __launch_bounds__(512, 2) void k_scan(
    const float4* __restrict__ v, const float4* __restrict__ x,
    const float4* __restrict__ v0, const float* __restrict__ sw,
    float4* __restrict__ out)
{
    __shared__ float4 sm[SUBS * DQ];     // aggregates -> exclusive prefixes (in place)
    __shared__ float4 carry_sm[DQ];

    const int tid  = threadIdx.x;
    const int dq   = tid & 15;
    const int sub  = tid >> 4;
    const int tile = blockIdx.x;
    const int bh   = blockIdx.y;
    const int h    = bh & (NH - 1);
    const int b    = bh >> 3;

    const float a  = 1.0f / (1.0f + expf(-sw[h]));
    const float om = 1.0f - a;
    const float cf = a * (om / fmaxf(om, 1e-6f));
    float a8 = a;                                    // a^8
    #pragma unroll
    for (int i = 0; i < 3; ++i) a8 *= a8;
    float a256 = a;                                  // a^256 = a^TILE_T
    #pragma unroll
    for (int i = 0; i < 8; ++i) a256 *= a256;

    const int t0   = tile * TILE_T + sub * L;
    const int base = ((b * NT + t0) * NH + h) * (ND / 4) + dq;

    // ---- local scan of L steps, zero-seeded, kept in registers ----
    float4 y[L];
    float4 yy = make_float4(0.f, 0.f, 0.f, 0.f);
    #pragma unroll
    for (int i = 0; i < L; ++i) {
        float4 vv = v[base + i * F4T];
        float4 xx = x[base + i * F4T];
        yy.x = fmaf(a, yy.x, fmaf(om, vv.x, cf * xx.x));
        yy.y = fmaf(a, yy.y, fmaf(om, vv.y, cf * xx.y));
        yy.z = fmaf(a, yy.z, fmaf(om, vv.z, cf * xx.z));
        yy.w = fmaf(a, yy.w, fmaf(om, vv.w, cf * xx.w));
        y[i] = yy;
    }
    sm[sub * DQ + dq] = yy;              // sub-chunk aggregate
    __syncthreads();

    // ---- in-block scan across sub-chunks + lookback (first 16 threads) ----
    if (tid < DQ) {
        float4 I = make_float4(0.f, 0.f, 0.f, 0.f);
        #pragma unroll
        for (int k = 0; k < SUBS; ++k) {
            float4 t4 = sm[k * DQ + tid];
            sm[k * DQ + tid] = I;        // exclusive prefix
            I.x = fmaf(a8, I.x, t4.x);
            I.y = fmaf(a8, I.y, t4.y);
            I.z = fmaf(a8, I.z, t4.z);
            I.w = fmaf(a8, I.w, t4.w);
        }
        const float4 blockagg = I;
        const int sidx = (tile * NBH + bh) * DQ + tid;
        const int fidx = tile * NBH + bh;

        if (tile > 0) {                  // publish aggregate ASAP
            __stcg(&g_S[sidx], blockagg);
            __syncwarp(0x0000FFFFu);
            if (tid == 0) st_release(&g_flag[fidx], 1);
        }

        // lookback for the tile-entry carry
        float4 carry;
        if (tile == 0) {
            carry = __ldg(&v0[h * DQ + tid]);
        } else {
            float4 acc = make_float4(0.f, 0.f, 0.f, 0.f);
            float  d   = 1.0f;
            int    j   = tile - 1;
            for (;;) {
                int f = 0;
                if (tid == 0) {
                    do { f = ld_acquire(&g_flag[j * NBH + bh]); } while (f == 0);
                }
                f = __shfl_sync(0x0000FFFFu, f, 0);
                const int pidx = (j * NBH + bh) * DQ + tid;
                if (f == 2) {
                    float4 Y = __ldcg(&g_Y[pidx]);
                    carry.x = fmaf(d, Y.x, acc.x);
                    carry.y = fmaf(d, Y.y, acc.y);
                    carry.z = fmaf(d, Y.z, acc.z);
                    carry.w = fmaf(d, Y.w, acc.w);
                    break;
                } else {
                    float4 S = __ldcg(&g_S[pidx]);
                    acc.x = fmaf(d, S.x, acc.x);
                    acc.y = fmaf(d, S.y, acc.y);
                    acc.z = fmaf(d, S.z, acc.z);
                    acc.w = fmaf(d, S.w, acc.w);
                    d *= a256;
                    --j;
                }
            }
        }

        // publish inclusive end value
        float4 ye;
        ye.x = fmaf(a256, carry.x, blockagg.x);
        ye.y = fmaf(a256, carry.y, blockagg.y);
        ye.z = fmaf(a256, carry.z, blockagg.z);
        ye.w = fmaf(a256, carry.w, blockagg.w);
        __stcg(&g_Y[sidx], ye);
        __syncwarp(0x0000FFFFu);
        if (tid == 0) st_release(&g_flag[fidx], 2);

        carry_sm[tid] = carry;
    }
    __syncthreads();

    // ---- apply carry in registers and write output (single store pass) ----
    const float4 carry = carry_sm[dq];
    float p = 1.0f;                       // a^(8*sub)
    for (int k = 0; k < sub; ++k) p *= a8;
    const float4 E = sm[sub * DQ + dq];   // within-block exclusive prefix
    float4 c;
    c.x = fmaf(p, carry.x, E.x);
    c.y = fmaf(p, carry.y, E.y);
    c.z = fmaf(p, carry.z, E.z);
    c.w = fmaf(p, carry.w, E.w);

    float pa = a;
    #pragma unroll
    for (int i = 0; i < L; ++i) {
        float4 o;
        o.x = fmaf(pa, c.x, y[i].x);
        o.y = fmaf(pa, c.y, y[i].y);
        o.z = fmaf(pa, c.z, y[i].z);
        o.w = fmaf(pa, c.w, y[i].w);
        out[base + i * F4T] = o;
        pa *= a;
    }
}

extern "C" void kernel_launch(void* const* d_in, const int* in_sizes, int n_in,
                              void* d_out, int out_size)
{
    const float4* v  = (const float4*)d_in[0];   // values   [B,T,H,D] f32
    const float4* x  = (const float4*)d_in[1];   // aux      [B,T,H,D] f32
    const float4* v0 = (const float4*)d_in[2];   // v0       [1,1,H,D] f32
    const float*  sw = (const float*)d_in[3];    // weight   [H,1]     f32

    k_zero<<<1, NTILES * NBH>>>();
    k_scan<<<dim3(NTILES, NBH), SUBS * DQ>>>(v, x, (const float4*)v0, sw, (float4*)d_out);
}